// round 13
// baseline (speedup 1.0000x reference)
#include <cuda_runtime.h>

#define H 1024
#define S 65536

// streaming geometry: warp-per-row, 16 rows per block
#define K2B   512
#define RPB   16
#define NB2   (S / RPB)        // 4096 streaming blocks

// k1 geometry
#define ISL   64               // W i-slices
#define IROWS (H / ISL)        // 16 rows each

#define NEG_INF (-3.402823466e38f)

// ---- device scratch (no allocation allowed) ----
__device__ float    g_vpart[ISL * H];
__device__ float    g_v[H];
__device__ float    g_scores[S];
__device__ float2   g_pairs[NB2];     // per-block online (max, expsum)
__device__ float    g_gm, g_gs;       // merged global softmax stats
__device__ unsigned g_done1;          // zero-init; reset after use (replay-safe)
__device__ unsigned g_done2;

// ---------------------------------------------------------------------------
// k1: partial v over 64 i-slices (16 W-rows each, all 1024 j's), then the
// LAST block to finish reduces the 64 partials in fixed order (deterministic
// regardless of which block is last) and resets the counter for graph replay.
// ---------------------------------------------------------------------------
__global__ __launch_bounds__(1024) void k1_compute_v(const float* __restrict__ hidden,
                                                     const float* __restrict__ W) {
    const int i0 = blockIdx.x * IROWS;
    const int j  = threadIdx.x;
    float a0 = 0.f, a1 = 0.f, a2 = 0.f, a3 = 0.f;
    #pragma unroll
    for (int k = 0; k < IROWS; k += 4) {
        a0 = fmaf(__ldg(&hidden[i0 + k + 0]), W[(size_t)(i0 + k + 0) * H + j], a0);
        a1 = fmaf(__ldg(&hidden[i0 + k + 1]), W[(size_t)(i0 + k + 1) * H + j], a1);
        a2 = fmaf(__ldg(&hidden[i0 + k + 2]), W[(size_t)(i0 + k + 2) * H + j], a2);
        a3 = fmaf(__ldg(&hidden[i0 + k + 3]), W[(size_t)(i0 + k + 3) * H + j], a3);
    }
    g_vpart[blockIdx.x * H + j] = (a0 + a1) + (a2 + a3);

    // last-block-done: canonical threadFenceReduction pattern
    __threadfence();
    __syncthreads();
    __shared__ unsigned amLast;
    if (j == 0) amLast = (atomicAdd(&g_done1, 1u) == ISL - 1u);
    __syncthreads();
    if (amLast) {
        __threadfence();
        float b0 = 0.f, b1 = 0.f, b2 = 0.f, b3 = 0.f;
        #pragma unroll
        for (int s = 0; s < ISL; s += 4) {       // fixed order -> deterministic
            b0 += __ldcg(&g_vpart[(s + 0) * H + j]);
            b1 += __ldcg(&g_vpart[(s + 1) * H + j]);
            b2 += __ldcg(&g_vpart[(s + 2) * H + j]);
            b3 += __ldcg(&g_vpart[(s + 3) * H + j]);
        }
        g_v[j] = (b0 + b1) + (b2 + b3);
        if (j == 0) g_done1 = 0u;                // reset for next graph replay
    }
}

// ---------------------------------------------------------------------------
// k2: the 256 MB streaming pass (UNCHANGED hot loop: warp-per-row, float4,
// __ldcs, 4 CTAs/SM). Each block emits one online (m, s) pair; the LAST
// block to finish merges all 4096 pairs in fixed order into g_gm/g_gs.
// ---------------------------------------------------------------------------
__global__ __launch_bounds__(K2B, 4) void k2_scores(const float* __restrict__ enc) {
    __shared__ float4 sv[H / 4];
    __shared__ float wsc[RPB];
    const int tid  = threadIdx.x;
    const int warp = tid >> 5;
    const int lane = tid & 31;

    if (tid < H / 4) sv[tid] = reinterpret_cast<const float4*>(g_v)[tid];
    __syncthreads();

    const int row = blockIdx.x * RPB + warp;
    const float4* __restrict__ r4 =
        reinterpret_cast<const float4*>(enc + (size_t)row * H);

    float x0 = 0.f, x1 = 0.f;
    #pragma unroll
    for (int k = 0; k < 8; k++) {
        float4 a  = __ldcs(&r4[k * 32 + lane]);
        float4 vv = sv[k * 32 + lane];
        x0 = fmaf(a.x, vv.x, x0);
        x1 = fmaf(a.y, vv.y, x1);
        x0 = fmaf(a.z, vv.z, x0);
        x1 = fmaf(a.w, vv.w, x1);
    }
    float acc = x0 + x1;
    #pragma unroll
    for (int o = 16; o > 0; o >>= 1)
        acc += __shfl_xor_sync(0xffffffffu, acc, o);

    if (lane == 0) {
        g_scores[row] = acc;
        wsc[warp] = acc;
    }
    __syncthreads();

    if (warp == 0 && lane < RPB) {               // 16 scores -> one (m, s) pair
        float sc = wsc[lane];
        float m = sc;
        #pragma unroll
        for (int o = 8; o > 0; o >>= 1)
            m = fmaxf(m, __shfl_xor_sync(0x0000ffffu, m, o));
        float e = __expf(sc - m);
        #pragma unroll
        for (int o = 8; o > 0; o >>= 1)
            e += __shfl_xor_sync(0x0000ffffu, e, o);
        if (lane == 0) g_pairs[blockIdx.x] = make_float2(m, e);
    }

    // last-block-done: merge the 4096 pairs (fixed order -> deterministic)
    __threadfence();
    __syncthreads();
    __shared__ unsigned amLast;
    if (tid == 0) amLast = (atomicAdd(&g_done2, 1u) == NB2 - 1u);
    __syncthreads();
    if (amLast) {
        __threadfence();
        __shared__ float smw[K2B / 32], sms[K2B / 32];
        float m = NEG_INF, s = 0.f;
        #pragma unroll
        for (int q = 0; q < NB2 / K2B; q++) {    // 8 pairs per thread, fixed order
            float2 p = __ldcg(&g_pairs[tid * (NB2 / K2B) + q]);
            float nm = fmaxf(m, p.x);
            s = s * __expf(m - nm) + p.y * __expf(p.x - nm);
            m = nm;
        }
        #pragma unroll
        for (int o = 16; o > 0; o >>= 1) {
            float om = __shfl_xor_sync(0xffffffffu, m, o);
            float os = __shfl_xor_sync(0xffffffffu, s, o);
            float nm = fmaxf(m, om);
            s = s * __expf(m - nm) + os * __expf(om - nm);
            m = nm;
        }
        if (lane == 0) { smw[warp] = m; sms[warp] = s; }
        __syncthreads();
        if (warp == 0 && lane < K2B / 32) {
            float mm = smw[lane], ss = sms[lane];
            #pragma unroll
            for (int o = 8; o > 0; o >>= 1) {
                float om = __shfl_xor_sync(0x0000ffffu, mm, o);
                float os = __shfl_xor_sync(0x0000ffffu, ss, o);
                float nm = fmaxf(mm, om);
                ss = ss * __expf(mm - nm) + os * __expf(om - nm);
                mm = nm;
            }
            if (lane == 0) { g_gm = mm; g_gs = ss; g_done2 = 0u; }
        }
    }
}

// ---------------------------------------------------------------------------
// k3: trivial epilogue — read two scalars, stream 512 KB.
// ---------------------------------------------------------------------------
__global__ __launch_bounds__(512) void k3_epilogue(float* __restrict__ out) {
    const float gm  = g_gm;
    const float inv = 1.0f / g_gs;
    const int i = blockIdx.x * 512 + threadIdx.x;
    out[i] = __expf(g_scores[i] - gm) * inv;
}

// ---------------------------------------------------------------------------
extern "C" void kernel_launch(void* const* d_in, const int* in_sizes, int n_in,
                              void* d_out, int out_size) {
    const float* hidden = (const float*)d_in[0];   // [H]
    const float* enc    = (const float*)d_in[1];   // [S, H]
    const float* W      = (const float*)d_in[2];   // [H, H]
    // d_in[3] = b : softmax-shift-invariant, unused
    float* out = (float*)d_out;                    // [1,1,S] fp32

    k1_compute_v<<<ISL, 1024>>>(hidden, W);
    k2_scores<<<NB2, K2B>>>(enc);
    k3_epilogue<<<S / 512, 512>>>(out);
}

// round 15
// speedup vs baseline: 1.0043x; 1.0043x over previous
#include <cuda_runtime.h>

#define H 1024
#define S 65536

// streaming geometry: warp-per-row, 16 rows per block (UNCHANGED from R9 best)
#define K2B   512
#define RPB   16
#define NB2   (S / RPB)        // 4096 streaming blocks

// k1 geometry: 128 slices x 8 W-rows
#define ISL   128
#define IROWS (H / ISL)        // 8

// epilogue geometry: 128 blocks x 512 threads, 512 outputs each
#define EB    128
#define ETHR  512
#define PPT   (NB2 / ETHR)     // 8 pairs per thread

#define NEG_INF (-3.402823466e38f)

// ---- device scratch (no allocation allowed) ----
__device__ float  g_vpart[ISL * H];
__device__ float  g_v[H];
__device__ float  g_scores[S];
__device__ float2 g_pairs[NB2];      // per-block online (max, expsum)

// ---------------------------------------------------------------------------
// k1: partial v over 128 i-slices. block b: 8 W-rows, all 1024 j's.
// 4 MB of W spread across 128 SMs; no tail, no fences.
// ---------------------------------------------------------------------------
__global__ __launch_bounds__(1024) void k1_partial_v(const float* __restrict__ hidden,
                                                     const float* __restrict__ W) {
    const int i0 = blockIdx.x * IROWS;
    const int j  = threadIdx.x;
    float a0 = 0.f, a1 = 0.f, a2 = 0.f, a3 = 0.f;
    #pragma unroll
    for (int k = 0; k < IROWS; k += 4) {
        a0 = fmaf(__ldg(&hidden[i0 + k + 0]), W[(size_t)(i0 + k + 0) * H + j], a0);
        a1 = fmaf(__ldg(&hidden[i0 + k + 1]), W[(size_t)(i0 + k + 1) * H + j], a1);
        a2 = fmaf(__ldg(&hidden[i0 + k + 2]), W[(size_t)(i0 + k + 2) * H + j], a2);
        a3 = fmaf(__ldg(&hidden[i0 + k + 3]), W[(size_t)(i0 + k + 3) * H + j], a3);
    }
    g_vpart[blockIdx.x * H + j] = (a0 + a1) + (a2 + a3);
}

// k1b: v[j] = fixed-order sum of 128 partials. 4 blocks x 256.
__global__ __launch_bounds__(256) void k1b_reduce_v() {
    const int j = blockIdx.x * 256 + threadIdx.x;
    float a0 = 0.f, a1 = 0.f, a2 = 0.f, a3 = 0.f;
    #pragma unroll
    for (int s = 0; s < ISL; s += 4) {
        a0 += g_vpart[(s + 0) * H + j];
        a1 += g_vpart[(s + 1) * H + j];
        a2 += g_vpart[(s + 2) * H + j];
        a3 += g_vpart[(s + 3) * H + j];
    }
    g_v[j] = (a0 + a1) + (a2 + a3);
}

// ---------------------------------------------------------------------------
// k2: the 256 MB streaming pass — BYTE-IDENTICAL hot loop to the 49.7us best:
// warp-per-row, float4, __ldcs, __launch_bounds__(512,4). Emits one online
// (m, s) pair per block. No fences, no atomics, no tail work.
// ---------------------------------------------------------------------------
__global__ __launch_bounds__(K2B, 4) void k2_scores(const float* __restrict__ enc) {
    __shared__ float4 sv[H / 4];
    __shared__ float wsc[RPB];
    const int tid  = threadIdx.x;
    const int warp = tid >> 5;
    const int lane = tid & 31;

    if (tid < H / 4) sv[tid] = reinterpret_cast<const float4*>(g_v)[tid];
    __syncthreads();

    const int row = blockIdx.x * RPB + warp;
    const float4* __restrict__ r4 =
        reinterpret_cast<const float4*>(enc + (size_t)row * H);

    float x0 = 0.f, x1 = 0.f;
    #pragma unroll
    for (int k = 0; k < 8; k++) {
        float4 a  = __ldcs(&r4[k * 32 + lane]);
        float4 vv = sv[k * 32 + lane];
        x0 = fmaf(a.x, vv.x, x0);
        x1 = fmaf(a.y, vv.y, x1);
        x0 = fmaf(a.z, vv.z, x0);
        x1 = fmaf(a.w, vv.w, x1);
    }
    float acc = x0 + x1;
    #pragma unroll
    for (int o = 16; o > 0; o >>= 1)
        acc += __shfl_xor_sync(0xffffffffu, acc, o);

    if (lane == 0) {
        g_scores[row] = acc;
        wsc[warp] = acc;
    }
    __syncthreads();

    if (warp == 0 && lane < RPB) {           // 16 scores -> one (m, s) pair
        float sc = wsc[lane];
        float m = sc;
        #pragma unroll
        for (int o = 8; o > 0; o >>= 1)
            m = fmaxf(m, __shfl_xor_sync(0x0000ffffu, m, o));
        float e = __expf(sc - m);
        #pragma unroll
        for (int o = 8; o > 0; o >>= 1)
            e += __shfl_xor_sync(0x0000ffffu, e, o);
        if (lane == 0) g_pairs[blockIdx.x] = make_float2(m, e);
    }
}

// ---------------------------------------------------------------------------
// k3: fused epilogue at full-chip width. Each of 128 blocks redundantly
// merges the 4096 pairs (fixed order: 8/thread -> warp tree -> block tree;
// bitwise deterministic), then writes its 512 normalized outputs.
// ---------------------------------------------------------------------------
__global__ __launch_bounds__(ETHR) void k3_epilogue(float* __restrict__ out) {
    __shared__ float smw[ETHR / 32], sms[ETHR / 32];
    __shared__ float s_gm, s_gs;
    const int tid  = threadIdx.x;
    const int warp = tid >> 5;
    const int lane = tid & 31;

    float m = NEG_INF, s = 0.f;
    #pragma unroll
    for (int q = 0; q < PPT; q++) {          // fixed order -> deterministic
        float2 p = __ldcg(&g_pairs[tid * PPT + q]);
        float nm = fmaxf(m, p.x);
        s = s * __expf(m - nm) + p.y * __expf(p.x - nm);
        m = nm;
    }
    #pragma unroll
    for (int o = 16; o > 0; o >>= 1) {
        float om = __shfl_xor_sync(0xffffffffu, m, o);
        float os = __shfl_xor_sync(0xffffffffu, s, o);
        float nm = fmaxf(m, om);
        s = s * __expf(m - nm) + os * __expf(om - nm);
        m = nm;
    }
    if (lane == 0) { smw[warp] = m; sms[warp] = s; }
    __syncthreads();
    if (warp == 0 && lane < ETHR / 32) {
        float mm = smw[lane], ss = sms[lane];
        #pragma unroll
        for (int o = 8; o > 0; o >>= 1) {
            float om = __shfl_xor_sync(0x0000ffffu, mm, o);
            float os = __shfl_xor_sync(0x0000ffffu, ss, o);
            float nm = fmaxf(mm, om);
            ss = ss * __expf(mm - nm) + os * __expf(om - nm);
            mm = nm;
        }
        if (lane == 0) { s_gm = mm; s_gs = ss; }
    }
    __syncthreads();

    const float gm  = s_gm;
    const float inv = 1.0f / s_gs;
    const int i = blockIdx.x * ETHR + tid;
    out[i] = __expf(g_scores[i] - gm) * inv;
}

// ---------------------------------------------------------------------------
extern "C" void kernel_launch(void* const* d_in, const int* in_sizes, int n_in,
                              void* d_out, int out_size) {
    const float* hidden = (const float*)d_in[0];   // [H]
    const float* enc    = (const float*)d_in[1];   // [S, H]
    const float* W      = (const float*)d_in[2];   // [H, H]
    // d_in[3] = b : softmax-shift-invariant, unused
    float* out = (float*)d_out;                    // [1,1,S] fp32

    k1_partial_v<<<ISL, 1024>>>(hidden, W);
    k1b_reduce_v<<<H / 256, 256>>>();
    k2_scores<<<NB2, K2B>>>(enc);
    k3_epilogue<<<EB, ETHR>>>(out);
}